// round 9
// baseline (speedup 1.0000x reference)
#include <cuda_runtime.h>
#include <cuda_fp16.h>
#include <cstdint>

// ---------------- problem constants ----------------
#define NB      32
#define DIM     64
#define HW      1024
#define KCODES  2048
#define TOK_TILE 128
#define NBLOCKS  256          // TOKENS / TOK_TILE
#define NTILES   16           // KCODES / 128
#define BMARG    0.35f        // conservative |d2' - d_hi| bound (rigorous ~0.14)
#define WLIST    512          // per-warp candidate capacity

// ---------------- dynamic smem layout (bytes) ----------------
#define A_STRIDE 132
#define A_OFF    0u                       // fp32 A [64][132]  (33792 B)
#define B_OFF    33792u                   // 2 buffers x 16KB hi-only packed tiles
#define B_BUF    16384u
#define CN_OFF   66560u                   // 2 x 128 floats
#define DW_OFF   67584u                   // 192 floats
#define DB_OFF   68352u                   // 4 floats
#define CNT_OFF  68368u                   // 8 u32 per-warp counters
#define LIST_OFF 68400u                   // 8 x WLIST u32
#define TOKMIN_OFF 84784u                 // 128 u64
#define RED_OFF  85808u                   // 512 floats
#define SMEM_TOTAL 88064u

__device__ float g_cnorm[KCODES];
__device__ float g_partial[2 * NBLOCKS];
__device__ unsigned int g_done = 0;
// packed fp16 HI codebook: per tile 4096 u32
// addr(u32) = nt*256 + lane*8 + kk*2 + r   (r: b0/b1 regs of m16n8k16 B frag)
__device__ uint32_t g_cbf[NTILES * 4096];

// ---------------- helpers ----------------
__device__ __forceinline__ uint32_t smem_u32(const void* p) {
    uint32_t a;
    asm("{ .reg .u64 t; cvta.to.shared.u64 t, %1; cvt.u32.u64 %0, t; }" : "=r"(a) : "l"(p));
    return a;
}
__device__ __forceinline__ uint32_t packh2(float x, float y) {
    __half2 h = __floats2half2_rn(x, y);
    return *reinterpret_cast<uint32_t*>(&h);
}
__device__ __forceinline__ void mma_f16(float* d, const uint32_t* a,
                                        uint32_t b0, uint32_t b1) {
    asm volatile(
        "mma.sync.aligned.m16n8k16.row.col.f32.f16.f16.f32 "
        "{%0,%1,%2,%3}, {%4,%5,%6,%7}, {%8,%9}, {%0,%1,%2,%3};"
        : "+f"(d[0]), "+f"(d[1]), "+f"(d[2]), "+f"(d[3])
        : "r"(a[0]), "r"(a[1]), "r"(a[2]), "r"(a[3]), "r"(b0), "r"(b1));
}
__device__ __forceinline__ void cp16(uint32_t s, const void* g) {
    asm volatile("cp.async.cg.shared.global [%0], [%1], 16;" :: "r"(s), "l"(g));
}
__device__ __forceinline__ void cp_commit() {
    asm volatile("cp.async.commit_group;" ::: "memory");
}
__device__ __forceinline__ void cp_wait0() {
    asm volatile("cp.async.wait_group 0;" ::: "memory");
}
__device__ __forceinline__ uint32_t fkey(float v) {
    uint32_t b = __float_as_uint(v);
    return (b & 0x80000000u) ? ~b : (b | 0x80000000u);
}

// ---------------- prep: codebook norms + packed fp16 hi tiles ----------------
// grid 128: blk = tile*8 + sub. sub packs nt = sub*2 + {0,1}; 16 cnorm rows.
__global__ void __launch_bounds__(256) vq_prep(const float* __restrict__ cb) {
    int blk = blockIdx.x;
    int tile = blk >> 3;
    int sub = blk & 7;
    int tid = threadIdx.x;
    int lane = tid & 31;
    int grp  = tid >> 5;                  // 0..7

    if (tid < 16) {
        int k = tile * 128 + sub * 16 + tid;
        const float* r = cb + (size_t)k * DIM;
        float s = 0.f;
#pragma unroll
        for (int c4 = 0; c4 < DIM / 4; ++c4) {
            float4 v = *(const float4*)(r + c4 * 4);
            s += v.x * v.x + v.y * v.y + v.z * v.z + v.w * v.w;
        }
        g_cnorm[k] = s;
    }

    uint32_t* dsth = g_cbf + (size_t)tile * 4096;
    int nt = sub * 2 + (grp >> 2);        // 0..15
    int kk = grp & 3;                     // 0..3
    int code = tile * 128 + nt * 8 + (lane >> 2);
    int k0 = kk * 16 + (lane & 3) * 2;
    const float* row = cb + (size_t)code * DIM;
    dsth[nt * 256 + lane * 8 + kk * 2 + 0] = packh2(row[k0], row[k0 + 1]);
    dsth[nt * 256 + lane * 8 + kk * 2 + 1] = packh2(row[k0 + 8], row[k0 + 9]);
}

// ---------------- main kernel (finalize folded in) ----------------
__global__ void __launch_bounds__(256, 2)
vq_main(const float* __restrict__ lat, const float* __restrict__ tgt,
        const float* __restrict__ cb, const float* __restrict__ dw,
        const float* __restrict__ db, float* __restrict__ out, int out_size) {
    extern __shared__ char sm[];
    float* As = (float*)(sm + A_OFF);
    const uint32_t smem_base = smem_u32(sm);
    uint32_t* scnt = (uint32_t*)(sm + CNT_OFF);
    unsigned long long* tokmin = (unsigned long long*)(sm + TOKMIN_OFF);
    const int tid = threadIdx.x;
    const int lane = tid & 31;
    const int w = tid >> 5;
    const int gid = lane >> 2;           // 0..7  token-row group
    const int tig = lane & 3;            // 0..3  col group
    const int blk = blockIdx.x;
    const int n = blk >> 3;
    const int hw0 = (blk & 7) * TOK_TILE;
    const int h = w >> 2;                // nt-half (0..1)
    const int tgrp = w & 3;              // token group: tokens tgrp*32..+32
    uint32_t* wl = (uint32_t*)(sm + LIST_OFF) + w * WLIST;

    if (tid < 192) ((float*)(sm + DW_OFF))[tid] = dw[tid];
    if (tid < 3)   ((float*)(sm + DB_OFF))[tid] = db[tid];
    if (tid < 8)   scnt[tid] = 0u;
    if (tid < 128) tokmin[tid] = ~0ull;

    // ---- stage A (fp32) [k][token] ----
    const float* latbase = lat + (size_t)n * DIM * HW + hw0;
    {
        int tl = tid & 31;
        int cgrp = tid >> 5;
#pragma unroll
        for (int p = 0; p < 8; ++p) {
            int c = p * 8 + cgrp;
            float4 v = *(const float4*)(latbase + (size_t)c * HW + tl * 4);
            *(float4*)&As[c * A_STRIDE + tl * 4] = v;
        }
    }

    // ---- preload B tile 0 + cn tile 0 ----
    {
        const float4* src = (const float4*)(g_cbf);
        uint32_t dst = smem_base + B_OFF;
#pragma unroll 4
        for (int idx = tid; idx < 1024; idx += 256)
            cp16(dst + (uint32_t)idx * 16u, src + idx);
        if (tid < 32)
            cp16(smem_base + CN_OFF + (uint32_t)tid * 16u,
                 ((const float4*)g_cnorm) + tid);
        cp_commit();
    }
    cp_wait0();
    __syncthreads();

    // ---- resident A hi fragments: 2 token groups of 16 ----
    uint32_t ahA[4][4], ahB[4][4];
    const int tA = tgrp * 32 + gid;      // rows tA, tA+8
    const int tB = tA + 16;              // rows tB, tB+8
#pragma unroll
    for (int kk = 0; kk < 4; ++kk) {
        int k0 = kk * 16 + tig * 2;
        ahA[kk][0] = packh2(As[(k0 + 0) * A_STRIDE + tA],     As[(k0 + 1) * A_STRIDE + tA]);
        ahA[kk][1] = packh2(As[(k0 + 0) * A_STRIDE + tA + 8], As[(k0 + 1) * A_STRIDE + tA + 8]);
        ahA[kk][2] = packh2(As[(k0 + 8) * A_STRIDE + tA],     As[(k0 + 9) * A_STRIDE + tA]);
        ahA[kk][3] = packh2(As[(k0 + 8) * A_STRIDE + tA + 8], As[(k0 + 9) * A_STRIDE + tA + 8]);
        ahB[kk][0] = packh2(As[(k0 + 0) * A_STRIDE + tB],     As[(k0 + 1) * A_STRIDE + tB]);
        ahB[kk][1] = packh2(As[(k0 + 0) * A_STRIDE + tB + 8], As[(k0 + 1) * A_STRIDE + tB + 8]);
        ahB[kk][2] = packh2(As[(k0 + 8) * A_STRIDE + tB],     As[(k0 + 9) * A_STRIDE + tB]);
        ahB[kk][3] = packh2(As[(k0 + 8) * A_STRIDE + tB + 8], As[(k0 + 9) * A_STRIDE + tB + 8]);
    }

    // running mins for the 4 token rows this thread covers
    float minv0 = 3.4e38f, minv1 = 3.4e38f, minv2 = 3.4e38f, minv3 = 3.4e38f;

    // 17 iterations: tiles 0..15, then tile 0 again (appends enabled from i=1)
    for (int i = 0; i <= NTILES; ++i) {
        int cur = i & 1;
        if (i < NTILES) {
            int nxt = (i + 1 == NTILES) ? 0 : i + 1;
            const float4* src = (const float4*)(g_cbf + (size_t)nxt * 4096);
            uint32_t dst = smem_base + B_OFF + (uint32_t)(cur ^ 1) * B_BUF;
#pragma unroll 4
            for (int idx = tid; idx < 1024; idx += 256)
                cp16(dst + (uint32_t)idx * 16u, src + idx);
            if (tid < 32)
                cp16(smem_base + CN_OFF + (uint32_t)(cur ^ 1) * 512u + (uint32_t)tid * 16u,
                     ((const float4*)(g_cnorm + nxt * 128)) + tid);
            cp_commit();
        }

        const char* smB = sm + B_OFF + (uint32_t)cur * B_BUF;
        const float* cns = (const float*)(sm + CN_OFF + (uint32_t)cur * 512u);
        const int ti = (i == NTILES) ? 0 : i;
        const int cbase = ti * 128;
        const bool appending = (i > 0);

#pragma unroll
        for (int nto = 0; nto < 8; ++nto) {
            int nt = h * 8 + nto;
            const uint4* bp = (const uint4*)(smB + ((size_t)nt * 256 + lane * 8) * 4);
            uint4 q0 = bp[0];             // kk0 (x,y), kk1 (z,w)
            uint4 q1 = bp[1];             // kk2 (x,y), kk3 (z,w)

            float dA0[4] = {0.f, 0.f, 0.f, 0.f};
            float dA1[4] = {0.f, 0.f, 0.f, 0.f};
            float dB0[4] = {0.f, 0.f, 0.f, 0.f};
            float dB1[4] = {0.f, 0.f, 0.f, 0.f};
            mma_f16(dA0, ahA[0], q0.x, q0.y);
            mma_f16(dB0, ahB[0], q0.x, q0.y);
            mma_f16(dA1, ahA[2], q1.x, q1.y);
            mma_f16(dB1, ahB[2], q1.x, q1.y);
            mma_f16(dA0, ahA[1], q0.z, q0.w);
            mma_f16(dB0, ahB[1], q0.z, q0.w);
            mma_f16(dA1, ahA[3], q1.z, q1.w);
            mma_f16(dB1, ahB[3], q1.z, q1.w);

            float2 cn2 = *(const float2*)(cns + nt * 8 + tig * 2);
            int c0 = cbase + nt * 8 + tig * 2;
            float vA0 = fmaf(-2.f, dA0[0] + dA1[0], cn2.x);
            float vA1 = fmaf(-2.f, dA0[1] + dA1[1], cn2.y);
            float vA2 = fmaf(-2.f, dA0[2] + dA1[2], cn2.x);
            float vA3 = fmaf(-2.f, dA0[3] + dA1[3], cn2.y);
            float vB0 = fmaf(-2.f, dB0[0] + dB1[0], cn2.x);
            float vB1 = fmaf(-2.f, dB0[1] + dB1[1], cn2.y);
            float vB2 = fmaf(-2.f, dB0[2] + dB1[2], cn2.x);
            float vB3 = fmaf(-2.f, dB0[3] + dB1[3], cn2.y);

            float lim0 = minv0 + BMARG, lim1 = minv1 + BMARG;
            float lim2 = minv2 + BMARG, lim3 = minv3 + BMARG;
            bool pass = (vA0 < lim0) | (vA1 < lim0) | (vA2 < lim1) | (vA3 < lim1)
                      | (vB0 < lim2) | (vB1 < lim2) | (vB2 < lim3) | (vB3 < lim3);
            if (appending) {
                if (__any_sync(0xFFFFFFFFu, pass)) {
                    if (vA0 < lim0) { uint32_t p = atomicAdd(&scnt[w], 1u); if (p < WLIST) wl[p] = ((uint32_t)tA << 11) | (uint32_t)c0; }
                    if (vA1 < lim0) { uint32_t p = atomicAdd(&scnt[w], 1u); if (p < WLIST) wl[p] = ((uint32_t)tA << 11) | (uint32_t)(c0 + 1); }
                    if (vA2 < lim1) { uint32_t p = atomicAdd(&scnt[w], 1u); if (p < WLIST) wl[p] = ((uint32_t)(tA + 8) << 11) | (uint32_t)c0; }
                    if (vA3 < lim1) { uint32_t p = atomicAdd(&scnt[w], 1u); if (p < WLIST) wl[p] = ((uint32_t)(tA + 8) << 11) | (uint32_t)(c0 + 1); }
                    if (vB0 < lim2) { uint32_t p = atomicAdd(&scnt[w], 1u); if (p < WLIST) wl[p] = ((uint32_t)tB << 11) | (uint32_t)c0; }
                    if (vB1 < lim2) { uint32_t p = atomicAdd(&scnt[w], 1u); if (p < WLIST) wl[p] = ((uint32_t)tB << 11) | (uint32_t)(c0 + 1); }
                    if (vB2 < lim3) { uint32_t p = atomicAdd(&scnt[w], 1u); if (p < WLIST) wl[p] = ((uint32_t)(tB + 8) << 11) | (uint32_t)c0; }
                    if (vB3 < lim3) { uint32_t p = atomicAdd(&scnt[w], 1u); if (p < WLIST) wl[p] = ((uint32_t)(tB + 8) << 11) | (uint32_t)(c0 + 1); }
                }
            }
            minv0 = fminf(minv0, fminf(vA0, vA1));
            minv1 = fminf(minv1, fminf(vA2, vA3));
            minv2 = fminf(minv2, fminf(vB0, vB1));
            minv3 = fminf(minv3, fminf(vB2, vB3));
        }
        // combine running min across the 4 col-threads of each token row
        minv0 = fminf(minv0, __shfl_xor_sync(0xFFFFFFFFu, minv0, 1));
        minv0 = fminf(minv0, __shfl_xor_sync(0xFFFFFFFFu, minv0, 2));
        minv1 = fminf(minv1, __shfl_xor_sync(0xFFFFFFFFu, minv1, 1));
        minv1 = fminf(minv1, __shfl_xor_sync(0xFFFFFFFFu, minv1, 2));
        minv2 = fminf(minv2, __shfl_xor_sync(0xFFFFFFFFu, minv2, 1));
        minv2 = fminf(minv2, __shfl_xor_sync(0xFFFFFFFFu, minv2, 2));
        minv3 = fminf(minv3, __shfl_xor_sync(0xFFFFFFFFu, minv3, 1));
        minv3 = fminf(minv3, __shfl_xor_sync(0xFFFFFFFFu, minv3, 2));

        cp_wait0();
        __syncthreads();
    }

    // ---- exact fp32 refinement (each warp refines its own list) ----
    {
        uint32_t mycnt = scnt[w];
        if (mycnt > WLIST) mycnt = WLIST;
        for (uint32_t idx = lane; idx < mycnt; idx += 32) {
            uint32_t e = wl[idx];
            int t = (int)(e >> 11);
            int c = (int)(e & 2047u);
            const float4* er = (const float4*)(cb + (size_t)c * DIM);
            float dot = 0.f;
#pragma unroll
            for (int k4 = 0; k4 < 16; ++k4) {
                float4 ev = er[k4];
                dot += ev.x * As[(k4 * 4 + 0) * A_STRIDE + t]
                     + ev.y * As[(k4 * 4 + 1) * A_STRIDE + t]
                     + ev.z * As[(k4 * 4 + 2) * A_STRIDE + t]
                     + ev.w * As[(k4 * 4 + 3) * A_STRIDE + t];
            }
            float val = g_cnorm[c] - 2.0f * dot;
            unsigned long long pk = ((unsigned long long)fkey(val) << 32) | (unsigned)c;
            atomicMin(&tokmin[t], pk);
        }
    }
    __syncthreads();

    // ---- exact fp32 epilogue ----
    float my_vq = 0.f, my_rc = 0.f;
    if (tid < TOK_TILE) {
        int bi = (int)(tokmin[tid] & 0xFFFFFFFFu);
        const float* q = cb + (size_t)bi * DIM;
        const float* dws = (const float*)(sm + DW_OFF);
        const float* dbs = (const float*)(sm + DB_OFF);
        float y0 = dbs[0], y1 = dbs[1], y2 = dbs[2];
        float vq = 0.f;
#pragma unroll
        for (int c4 = 0; c4 < DIM / 4; ++c4) {
            float4 qv = *(const float4*)(q + c4 * 4);
            float qa[4] = {qv.x, qv.y, qv.z, qv.w};
#pragma unroll
            for (int r = 0; r < 4; ++r) {
                int c = c4 * 4 + r;
                float xc = As[c * A_STRIDE + tid];
                float dd = xc - qa[r];
                vq += dd * dd;
                y0 += dws[c] * qa[r];
                y1 += dws[DIM + c] * qa[r];
                y2 += dws[2 * DIM + c] * qa[r];
            }
        }
        const float* tg = tgt + (size_t)n * 3 * HW + hw0 + tid;
        float e0 = y0 - tg[0];
        float e1 = y1 - tg[HW];
        float e2 = y2 - tg[2 * HW];
        my_vq = vq;
        my_rc = e0 * e0 + e1 * e1 + e2 * e2;
    }
    __syncthreads();
    float* sv = (float*)(sm + RED_OFF);
    float* sr = sv + 256;
    sv[tid] = my_vq;
    sr[tid] = my_rc;
    __syncthreads();
    for (int s = 128; s > 0; s >>= 1) {
        if (tid < s) { sv[tid] += sv[tid + s]; sr[tid] += sr[tid + s]; }
        __syncthreads();
    }
    if (tid == 0) {
        g_partial[blk] = sv[0];
        g_partial[NBLOCKS + blk] = sr[0];
    }

    // ---- last-block finalize (deterministic) ----
    __shared__ bool s_last;
    __threadfence();
    if (tid == 0) {
        unsigned v = atomicAdd(&g_done, 1u);
        s_last = (v == NBLOCKS - 1);
    }
    __syncthreads();
    if (s_last) {
        float v = g_partial[tid];
        float r = g_partial[NBLOCKS + tid];
        __syncthreads();
        sv[tid] = v;
        sr[tid] = r;
        __syncthreads();
        for (int s = 128; s > 0; s >>= 1) {
            if (tid < s) { sv[tid] += sv[tid + s]; sr[tid] += sr[tid + s]; }
            __syncthreads();
        }
        for (int idx = tid; idx < out_size; idx += 256)
            if (idx >= 3) out[idx] = 0.f;
        if (tid == 0) {
            float vq_loss = 2.0f * sv[0] / (float)(NB * DIM * HW);
            float recon = sr[0] / (float)(NB * 3 * HW);
            if (out_size > 0) out[0] = vq_loss + recon;
            if (out_size > 1) out[1] = vq_loss;
            if (out_size > 2) out[2] = recon;
            g_done = 0;   // reset for next launch/replay
        }
    }
}

extern "C" void kernel_launch(void* const* d_in, const int* in_sizes, int n_in,
                              void* d_out, int out_size) {
    const float* lat = (const float*)d_in[0];
    const float* tgt = (const float*)d_in[1];
    const float* cb  = (const float*)d_in[2];
    const float* dw  = (const float*)d_in[3];
    const float* db  = (const float*)d_in[4];
    float* out = (float*)d_out;

    vq_prep<<<128, 256>>>(cb);

    cudaFuncSetAttribute(vq_main, cudaFuncAttributeMaxDynamicSharedMemorySize, SMEM_TOTAL);
    vq_main<<<NBLOCKS, 256, SMEM_TOTAL>>>(lat, tgt, cb, dw, db, out, out_size);
}

// round 10
// speedup vs baseline: 1.0242x; 1.0242x over previous
#include <cuda_runtime.h>
#include <cuda_fp16.h>
#include <cstdint>

// ---------------- problem constants ----------------
#define NB      32
#define DIM     64
#define HW      1024
#define KCODES  2048
#define TOK_TILE 128
#define NBLOCKS  256          // TOKENS / TOK_TILE
#define NTILES   16           // KCODES / 128
#define BMARG    0.35f        // conservative |d2' - d_hi| bound (rigorous ~0.14)
#define WLIST    512          // per-warp candidate capacity

// ---------------- dynamic smem layout (bytes) ----------------
#define A_STRIDE 132
#define A_OFF    0u                       // fp32 A [64][132]  (33792 B)
#define B_OFF    33792u                   // 2 buffers x 16KB hi-only packed tiles
#define B_BUF    16384u
#define CN_OFF   66560u                   // 2 x 128 floats
#define DW_OFF   67584u                   // 192 floats
#define DB_OFF   68352u                   // 4 floats
#define CNT_OFF  68368u                   // 8 u32 per-warp counters
#define LIST_OFF 68400u                   // 8 x WLIST u32
#define TOKMIN_OFF 84784u                 // 128 u64
#define RED_OFF  85808u                   // 512 floats
#define SMEM_TOTAL 88064u

__device__ float g_cnorm[KCODES];
__device__ float g_partial[2 * NBLOCKS];
__device__ unsigned int g_done = 0;
// packed fp16 HI codebook: per tile 4096 u32
// addr(u32) = nt*256 + lane*8 + kk*2 + r   (r: b0/b1 regs of m16n8k16 B frag)
__device__ uint32_t g_cbf[NTILES * 4096];

// ---------------- helpers ----------------
__device__ __forceinline__ uint32_t smem_u32(const void* p) {
    uint32_t a;
    asm("{ .reg .u64 t; cvta.to.shared.u64 t, %1; cvt.u32.u64 %0, t; }" : "=r"(a) : "l"(p));
    return a;
}
__device__ __forceinline__ uint32_t packh2(float x, float y) {
    __half2 h = __floats2half2_rn(x, y);
    return *reinterpret_cast<uint32_t*>(&h);
}
__device__ __forceinline__ void mma_f16(float* d, const uint32_t* a,
                                        uint32_t b0, uint32_t b1) {
    asm volatile(
        "mma.sync.aligned.m16n8k16.row.col.f32.f16.f16.f32 "
        "{%0,%1,%2,%3}, {%4,%5,%6,%7}, {%8,%9}, {%0,%1,%2,%3};"
        : "+f"(d[0]), "+f"(d[1]), "+f"(d[2]), "+f"(d[3])
        : "r"(a[0]), "r"(a[1]), "r"(a[2]), "r"(a[3]), "r"(b0), "r"(b1));
}
__device__ __forceinline__ void cp16(uint32_t s, const void* g) {
    asm volatile("cp.async.cg.shared.global [%0], [%1], 16;" :: "r"(s), "l"(g));
}
__device__ __forceinline__ void cp_commit() {
    asm volatile("cp.async.commit_group;" ::: "memory");
}
__device__ __forceinline__ void cp_wait0() {
    asm volatile("cp.async.wait_group 0;" ::: "memory");
}
__device__ __forceinline__ uint32_t fkey(float v) {
    uint32_t b = __float_as_uint(v);
    return (b & 0x80000000u) ? ~b : (b | 0x80000000u);
}

// ---------------- prep: codebook norms + packed fp16 hi tiles ----------------
// grid 128: blk = tile*8 + sub. sub packs nt = sub*2 + {0,1}; 16 cnorm rows.
__global__ void __launch_bounds__(256) vq_prep(const float* __restrict__ cb) {
    int blk = blockIdx.x;
    int tile = blk >> 3;
    int sub = blk & 7;
    int tid = threadIdx.x;
    int lane = tid & 31;
    int grp  = tid >> 5;                  // 0..7

    if (tid < 16) {
        int k = tile * 128 + sub * 16 + tid;
        const float* r = cb + (size_t)k * DIM;
        float s = 0.f;
#pragma unroll
        for (int c4 = 0; c4 < DIM / 4; ++c4) {
            float4 v = *(const float4*)(r + c4 * 4);
            s += v.x * v.x + v.y * v.y + v.z * v.z + v.w * v.w;
        }
        g_cnorm[k] = s;
    }

    uint32_t* dsth = g_cbf + (size_t)tile * 4096;
    int nt = sub * 2 + (grp >> 2);        // 0..15
    int kk = grp & 3;                     // 0..3
    int code = tile * 128 + nt * 8 + (lane >> 2);
    int k0 = kk * 16 + (lane & 3) * 2;
    const float* row = cb + (size_t)code * DIM;
    dsth[nt * 256 + lane * 8 + kk * 2 + 0] = packh2(row[k0], row[k0 + 1]);
    dsth[nt * 256 + lane * 8 + kk * 2 + 1] = packh2(row[k0 + 8], row[k0 + 9]);
}

// ---------------- main kernel (finalize folded in) ----------------
__global__ void __launch_bounds__(256, 2)
vq_main(const float* __restrict__ lat, const float* __restrict__ tgt,
        const float* __restrict__ cb, const float* __restrict__ dw,
        const float* __restrict__ db, float* __restrict__ out, int out_size) {
    extern __shared__ char sm[];
    float* As = (float*)(sm + A_OFF);
    const uint32_t smem_base = smem_u32(sm);
    uint32_t* scnt = (uint32_t*)(sm + CNT_OFF);
    unsigned long long* tokmin = (unsigned long long*)(sm + TOKMIN_OFF);
    const int tid = threadIdx.x;
    const int lane = tid & 31;
    const int w = tid >> 5;
    const int gid = lane >> 2;           // 0..7  token-row group
    const int tig = lane & 3;            // 0..3  col group
    const int blk = blockIdx.x;
    const int n = blk >> 3;
    const int hw0 = (blk & 7) * TOK_TILE;
    uint32_t* wl = (uint32_t*)(sm + LIST_OFF) + w * WLIST;

    if (tid < 192) ((float*)(sm + DW_OFF))[tid] = dw[tid];
    if (tid < 3)   ((float*)(sm + DB_OFF))[tid] = db[tid];
    if (tid < 8)   scnt[tid] = 0u;
    if (tid < 128) tokmin[tid] = ~0ull;

    // ---- stage A (fp32) [k][token] ----
    const float* latbase = lat + (size_t)n * DIM * HW + hw0;
    {
        int tl = tid & 31;
        int cgrp = tid >> 5;
#pragma unroll
        for (int p = 0; p < 8; ++p) {
            int c = p * 8 + cgrp;
            float4 v = *(const float4*)(latbase + (size_t)c * HW + tl * 4);
            *(float4*)&As[c * A_STRIDE + tl * 4] = v;
        }
    }

    // ---- preload B tile 0 + cn tile 0 ----
    {
        const float4* src = (const float4*)(g_cbf);
        uint32_t dst = smem_base + B_OFF;
#pragma unroll 4
        for (int idx = tid; idx < 1024; idx += 256)
            cp16(dst + (uint32_t)idx * 16u, src + idx);
        if (tid < 32)
            cp16(smem_base + CN_OFF + (uint32_t)tid * 16u,
                 ((const float4*)g_cnorm) + tid);
        cp_commit();
    }
    cp_wait0();
    __syncthreads();

    // ---- resident A hi fragments (R8 mapping: warp = 16 tokens x 128 codes) ----
    uint32_t ah[4][4];
    const int t0 = w * 16 + gid;
#pragma unroll
    for (int kk = 0; kk < 4; ++kk) {
        int k0 = kk * 16 + tig * 2;
        ah[kk][0] = packh2(As[(k0 + 0) * A_STRIDE + t0],     As[(k0 + 1) * A_STRIDE + t0]);
        ah[kk][1] = packh2(As[(k0 + 0) * A_STRIDE + t0 + 8], As[(k0 + 1) * A_STRIDE + t0 + 8]);
        ah[kk][2] = packh2(As[(k0 + 8) * A_STRIDE + t0],     As[(k0 + 9) * A_STRIDE + t0]);
        ah[kk][3] = packh2(As[(k0 + 8) * A_STRIDE + t0 + 8], As[(k0 + 9) * A_STRIDE + t0 + 8]);
    }

    float minv0 = 3.4e38f, minv1 = 3.4e38f;

    // 17 iterations: tiles 0..15, then tile 0 again (appends enabled from i=1)
    for (int i = 0; i <= NTILES; ++i) {
        int cur = i & 1;
        if (i < NTILES) {
            int nxt = (i + 1 == NTILES) ? 0 : i + 1;
            const float4* src = (const float4*)(g_cbf + (size_t)nxt * 4096);
            uint32_t dst = smem_base + B_OFF + (uint32_t)(cur ^ 1) * B_BUF;
#pragma unroll 4
            for (int idx = tid; idx < 1024; idx += 256)
                cp16(dst + (uint32_t)idx * 16u, src + idx);
            if (tid < 32)
                cp16(smem_base + CN_OFF + (uint32_t)(cur ^ 1) * 512u + (uint32_t)tid * 16u,
                     ((const float4*)(g_cnorm + nxt * 128)) + tid);
            cp_commit();
        }

        const char* smB = sm + B_OFF + (uint32_t)cur * B_BUF;
        const float* cns = (const float*)(sm + CN_OFF + (uint32_t)cur * 512u);
        const int ti = (i == NTILES) ? 0 : i;
        const int cbase = ti * 128;
        const bool appending = (i > 0);
        const uint4* bp = (const uint4*)smB;   // uint4 index = nt*64 + lane*2

        // software pipeline: preload nt-pair 0
        uint4 c0 = bp[lane * 2],       c1 = bp[lane * 2 + 1];        // nt 0: kk01, kk23
        uint4 c2 = bp[64 + lane * 2],  c3 = bp[64 + lane * 2 + 1];   // nt 1

#pragma unroll
        for (int ntp = 0; ntp < 8; ++ntp) {
            int nt = ntp * 2;
            uint4 n0, n1, n2, n3;
            if (ntp < 7) {
                n0 = bp[(nt + 2) * 64 + lane * 2];
                n1 = bp[(nt + 2) * 64 + lane * 2 + 1];
                n2 = bp[(nt + 3) * 64 + lane * 2];
                n3 = bp[(nt + 3) * 64 + lane * 2 + 1];
            }
            float dA0[4] = {0.f, 0.f, 0.f, 0.f};
            float dA1[4] = {0.f, 0.f, 0.f, 0.f};
            float dB0[4] = {0.f, 0.f, 0.f, 0.f};
            float dB1[4] = {0.f, 0.f, 0.f, 0.f};
            mma_f16(dA0, ah[0], c0.x, c0.y);
            mma_f16(dB0, ah[0], c2.x, c2.y);
            mma_f16(dA1, ah[2], c1.x, c1.y);
            mma_f16(dB1, ah[2], c3.x, c3.y);
            mma_f16(dA0, ah[1], c0.z, c0.w);
            mma_f16(dB0, ah[1], c2.z, c2.w);
            mma_f16(dA1, ah[3], c1.z, c1.w);
            mma_f16(dB1, ah[3], c3.z, c3.w);

            float2 cnA = *(const float2*)(cns + nt * 8 + tig * 2);
            float2 cnB = *(const float2*)(cns + (nt + 1) * 8 + tig * 2);
            int cA = cbase + nt * 8 + tig * 2;
            int cB = cA + 8;
            float vA0 = fmaf(-2.f, dA0[0] + dA1[0], cnA.x);
            float vA1 = fmaf(-2.f, dA0[1] + dA1[1], cnA.y);
            float vA2 = fmaf(-2.f, dA0[2] + dA1[2], cnA.x);
            float vA3 = fmaf(-2.f, dA0[3] + dA1[3], cnA.y);
            float vB0 = fmaf(-2.f, dB0[0] + dB1[0], cnB.x);
            float vB1 = fmaf(-2.f, dB0[1] + dB1[1], cnB.y);
            float vB2 = fmaf(-2.f, dB0[2] + dB1[2], cnB.x);
            float vB3 = fmaf(-2.f, dB0[3] + dB1[3], cnB.y);

            // row mins (reused for both pass-test and running-min update)
            float r0 = fminf(fminf(vA0, vA1), fminf(vB0, vB1));  // token t0
            float r1 = fminf(fminf(vA2, vA3), fminf(vB2, vB3));  // token t0+8
            bool pass = (r0 < minv0 + BMARG) | (r1 < minv1 + BMARG);
            if (appending) {
                if (__any_sync(0xFFFFFFFFu, pass)) {
                    float lim0 = minv0 + BMARG, lim1 = minv1 + BMARG;
                    if (vA0 < lim0) { uint32_t p = atomicAdd(&scnt[w], 1u); if (p < WLIST) wl[p] = ((uint32_t)t0 << 11) | (uint32_t)cA; }
                    if (vA1 < lim0) { uint32_t p = atomicAdd(&scnt[w], 1u); if (p < WLIST) wl[p] = ((uint32_t)t0 << 11) | (uint32_t)(cA + 1); }
                    if (vA2 < lim1) { uint32_t p = atomicAdd(&scnt[w], 1u); if (p < WLIST) wl[p] = ((uint32_t)(t0 + 8) << 11) | (uint32_t)cA; }
                    if (vA3 < lim1) { uint32_t p = atomicAdd(&scnt[w], 1u); if (p < WLIST) wl[p] = ((uint32_t)(t0 + 8) << 11) | (uint32_t)(cA + 1); }
                    if (vB0 < lim0) { uint32_t p = atomicAdd(&scnt[w], 1u); if (p < WLIST) wl[p] = ((uint32_t)t0 << 11) | (uint32_t)cB; }
                    if (vB1 < lim0) { uint32_t p = atomicAdd(&scnt[w], 1u); if (p < WLIST) wl[p] = ((uint32_t)t0 << 11) | (uint32_t)(cB + 1); }
                    if (vB2 < lim1) { uint32_t p = atomicAdd(&scnt[w], 1u); if (p < WLIST) wl[p] = ((uint32_t)(t0 + 8) << 11) | (uint32_t)cB; }
                    if (vB3 < lim1) { uint32_t p = atomicAdd(&scnt[w], 1u); if (p < WLIST) wl[p] = ((uint32_t)(t0 + 8) << 11) | (uint32_t)(cB + 1); }
                }
            }
            minv0 = fminf(minv0, r0);
            minv1 = fminf(minv1, r1);
            c0 = n0; c1 = n1; c2 = n2; c3 = n3;
        }
        // combine running min across the 4 col-threads of each token row
        minv0 = fminf(minv0, __shfl_xor_sync(0xFFFFFFFFu, minv0, 1));
        minv0 = fminf(minv0, __shfl_xor_sync(0xFFFFFFFFu, minv0, 2));
        minv1 = fminf(minv1, __shfl_xor_sync(0xFFFFFFFFu, minv1, 1));
        minv1 = fminf(minv1, __shfl_xor_sync(0xFFFFFFFFu, minv1, 2));

        cp_wait0();
        __syncthreads();
    }

    // ---- exact fp32 refinement (each warp refines its own list) ----
    {
        uint32_t mycnt = scnt[w];
        if (mycnt > WLIST) mycnt = WLIST;
        for (uint32_t idx = lane; idx < mycnt; idx += 32) {
            uint32_t e = wl[idx];
            int t = (int)(e >> 11);
            int c = (int)(e & 2047u);
            const float4* er = (const float4*)(cb + (size_t)c * DIM);
            float dot = 0.f;
#pragma unroll
            for (int k4 = 0; k4 < 16; ++k4) {
                float4 ev = er[k4];
                dot += ev.x * As[(k4 * 4 + 0) * A_STRIDE + t]
                     + ev.y * As[(k4 * 4 + 1) * A_STRIDE + t]
                     + ev.z * As[(k4 * 4 + 2) * A_STRIDE + t]
                     + ev.w * As[(k4 * 4 + 3) * A_STRIDE + t];
            }
            float val = g_cnorm[c] - 2.0f * dot;
            unsigned long long pk = ((unsigned long long)fkey(val) << 32) | (unsigned)c;
            atomicMin(&tokmin[t], pk);
        }
    }
    __syncthreads();

    // ---- exact fp32 epilogue ----
    float my_vq = 0.f, my_rc = 0.f;
    if (tid < TOK_TILE) {
        int bi = (int)(tokmin[tid] & 0xFFFFFFFFu);
        const float* q = cb + (size_t)bi * DIM;
        const float* dws = (const float*)(sm + DW_OFF);
        const float* dbs = (const float*)(sm + DB_OFF);
        float y0 = dbs[0], y1 = dbs[1], y2 = dbs[2];
        float vq = 0.f;
#pragma unroll
        for (int c4 = 0; c4 < DIM / 4; ++c4) {
            float4 qv = *(const float4*)(q + c4 * 4);
            float qa[4] = {qv.x, qv.y, qv.z, qv.w};
#pragma unroll
            for (int r = 0; r < 4; ++r) {
                int c = c4 * 4 + r;
                float xc = As[c * A_STRIDE + tid];
                float dd = xc - qa[r];
                vq += dd * dd;
                y0 += dws[c] * qa[r];
                y1 += dws[DIM + c] * qa[r];
                y2 += dws[2 * DIM + c] * qa[r];
            }
        }
        const float* tg = tgt + (size_t)n * 3 * HW + hw0 + tid;
        float e0 = y0 - tg[0];
        float e1 = y1 - tg[HW];
        float e2 = y2 - tg[2 * HW];
        my_vq = vq;
        my_rc = e0 * e0 + e1 * e1 + e2 * e2;
    }
    __syncthreads();
    float* sv = (float*)(sm + RED_OFF);
    float* sr = sv + 256;
    sv[tid] = my_vq;
    sr[tid] = my_rc;
    __syncthreads();
    for (int s = 128; s > 0; s >>= 1) {
        if (tid < s) { sv[tid] += sv[tid + s]; sr[tid] += sr[tid + s]; }
        __syncthreads();
    }
    if (tid == 0) {
        g_partial[blk] = sv[0];
        g_partial[NBLOCKS + blk] = sr[0];
    }

    // ---- last-block finalize (deterministic) ----
    __shared__ bool s_last;
    __threadfence();
    if (tid == 0) {
        unsigned v = atomicAdd(&g_done, 1u);
        s_last = (v == NBLOCKS - 1);
    }
    __syncthreads();
    if (s_last) {
        float v = g_partial[tid];
        float r = g_partial[NBLOCKS + tid];
        __syncthreads();
        sv[tid] = v;
        sr[tid] = r;
        __syncthreads();
        for (int s = 128; s > 0; s >>= 1) {
            if (tid < s) { sv[tid] += sv[tid + s]; sr[tid] += sr[tid + s]; }
            __syncthreads();
        }
        for (int idx = tid; idx < out_size; idx += 256)
            if (idx >= 3) out[idx] = 0.f;
        if (tid == 0) {
            float vq_loss = 2.0f * sv[0] / (float)(NB * DIM * HW);
            float recon = sr[0] / (float)(NB * 3 * HW);
            if (out_size > 0) out[0] = vq_loss + recon;
            if (out_size > 1) out[1] = vq_loss;
            if (out_size > 2) out[2] = recon;
            g_done = 0;   // reset for next launch/replay
        }
    }
}

extern "C" void kernel_launch(void* const* d_in, const int* in_sizes, int n_in,
                              void* d_out, int out_size) {
    const float* lat = (const float*)d_in[0];
    const float* tgt = (const float*)d_in[1];
    const float* cb  = (const float*)d_in[2];
    const float* dw  = (const float*)d_in[3];
    const float* db  = (const float*)d_in[4];
    float* out = (float*)d_out;

    vq_prep<<<128, 256>>>(cb);

    cudaFuncSetAttribute(vq_main, cudaFuncAttributeMaxDynamicSharedMemorySize, SMEM_TOTAL);
    vq_main<<<NBLOCKS, 256, SMEM_TOTAL>>>(lat, tgt, cb, dw, db, out, out_size);
}